// round 5
// baseline (speedup 1.0000x reference)
#include <cuda_runtime.h>
#include <cstdint>

// out[b, l] = x[b, perm[b, l]]   (B=1024, L=16384)
// Persistent CTAs (grid = 148), TRIPLE-buffered row staging via cp.async.bulk
// + mbarrier, 1024 threads/CTA (32 warps). Depth-3 pipeline keeps two TMA row
// loads in flight while one buffer is consumed; R4's depth-2/512-thread
// version stalled (occ 25%, DRAM 61%).

#define THREADS 1024
#define NBUF 3
#define NSM 148

__device__ __forceinline__ void mbar_wait(uint32_t mbar, uint32_t parity) {
    uint32_t done;
    asm volatile(
        "{\n\t.reg .pred P;\n\t"
        "mbarrier.try_wait.parity.acquire.cta.shared::cta.b64 P, [%1], %2;\n\t"
        "selp.b32 %0, 1, 0, P;\n\t}"
        : "=r"(done) : "r"(mbar), "r"(parity) : "memory");
    if (!done) {
        asm volatile(
            "{\n\t.reg .pred P;\n\t"
            "W_%=:\n\t"
            "mbarrier.try_wait.parity.acquire.cta.shared::cta.b64 P, [%0], %1, 0x989680;\n\t"
            "@P bra.uni D_%=;\n\t"
            "bra.uni W_%=;\n\t"
            "D_%=:\n\t}"
            :: "r"(mbar), "r"(parity) : "memory");
    }
}

__global__ __launch_bounds__(THREADS, 1)
void interleave_persist3_kernel(const float* __restrict__ x,
                                const int* __restrict__ perm,
                                float* __restrict__ out,
                                int L, int B, int grid) {
    extern __shared__ __align__(128) unsigned char smem_raw[];
    float* bufs[NBUF];
    bufs[0] = reinterpret_cast<float*>(smem_raw);
    bufs[1] = bufs[0] + L;
    bufs[2] = bufs[1] + L;
    uint64_t* mbars = reinterpret_cast<uint64_t*>(bufs[2] + L);

    uint32_t mb[NBUF], sb[NBUF];
    #pragma unroll
    for (int s = 0; s < NBUF; s++) {
        mb[s] = (uint32_t)__cvta_generic_to_shared(&mbars[s]);
        sb[s] = (uint32_t)__cvta_generic_to_shared(bufs[s]);
    }

    int tid = threadIdx.x;
    unsigned bytes = (unsigned)L * 4u;

    if (tid == 0) {
        #pragma unroll
        for (int s = 0; s < NBUF; s++)
            asm volatile("mbarrier.init.shared.b64 [%0], %1;" :: "r"(mb[s]), "r"(1) : "memory");
    }
    __syncthreads();

    // Prologue: TMAs for the first NBUF rows of this CTA.
    if (tid == 0) {
        #pragma unroll
        for (int s = 0; s < NBUF; s++) {
            long long row = (long long)blockIdx.x + (long long)s * grid;
            if (row < B) {
                asm volatile("mbarrier.arrive.expect_tx.shared.b64 _, [%0], %1;"
                             :: "r"(mb[s]), "r"(bytes) : "memory");
                asm volatile("cp.async.bulk.shared::cta.global.mbarrier::complete_tx::bytes "
                             "[%0], [%1], %2, [%3];"
                             :: "r"(sb[s]), "l"(x + row * L), "r"(bytes), "r"(mb[s]) : "memory");
            }
        }
    }

    int i = 0;
    for (long long r = blockIdx.x; r < B; r += grid, i++) {
        int b = i % NBUF;
        uint32_t ph = (uint32_t)((i / NBUF) & 1);
        const float* srow = bufs[b];

        // Prefetch perm (coalesced int4) while TMAs stream. L/4 = 4*THREADS.
        const int4* p4 = reinterpret_cast<const int4*>(perm + r * L);
        int4 p[4];
        #pragma unroll
        for (int j = 0; j < 4; j++) p[j] = p4[tid + j * THREADS];

        mbar_wait(mb[b], ph);

        // Gather whole share into registers, freeing the buffer.
        float4 o[4];
        #pragma unroll
        for (int j = 0; j < 4; j++) {
            o[j].x = srow[p[j].x];
            o[j].y = srow[p[j].y];
            o[j].z = srow[p[j].z];
            o[j].w = srow[p[j].w];
        }

        __syncthreads();  // all reads of buf[b] complete

        if (tid == 0) {
            long long nr = r + (long long)NBUF * grid;
            if (nr < B) {
                asm volatile("mbarrier.arrive.expect_tx.shared.b64 _, [%0], %1;"
                             :: "r"(mb[b]), "r"(bytes) : "memory");
                asm volatile("cp.async.bulk.shared::cta.global.mbarrier::complete_tx::bytes "
                             "[%0], [%1], %2, [%3];"
                             :: "r"(sb[b]), "l"(x + nr * L), "r"(bytes), "r"(mb[b]) : "memory");
            }
        }

        // Coalesced float4 stores overlap the two in-flight TMAs.
        float4* o4 = reinterpret_cast<float4*>(out + r * L);
        #pragma unroll
        for (int j = 0; j < 4; j++) o4[tid + j * THREADS] = o[j];
    }
}

extern "C" void kernel_launch(void* const* d_in, const int* in_sizes, int n_in,
                              void* d_out, int out_size) {
    const float* x   = (const float*)d_in[0];
    const int* perm  = (const int*)d_in[1];
    float* out       = (float*)d_out;

    long long total = (long long)in_sizes[1];
    int B = 1024;
    int L = (int)(total / B);

    size_t smem = (size_t)NBUF * L * sizeof(float) + 64;  // 192KB + mbarriers
    cudaFuncSetAttribute(interleave_persist3_kernel,
                         cudaFuncAttributeMaxDynamicSharedMemorySize, (int)smem);

    interleave_persist3_kernel<<<NSM, THREADS, smem>>>(x, perm, out, L, B, NSM);
}

// round 6
// speedup vs baseline: 1.2263x; 1.2263x over previous
#include <cuda_runtime.h>
#include <cstdint>

// out[b, l] = x[b, perm[b, l]]   (B=1024, L=16384)
// Two CTAs per row (grid = 2*B). Each CTA TMA-loads the FULL row into its own
// SMEM (the pair's duplicate read dedups in L2), then gathers/stores only its
// half. Finer work quanta -> 4.6 waves instead of 2.31 -> smaller tail.
// Streaming cache hints on perm loads / out stores.

#define THREADS 512

__global__ __launch_bounds__(THREADS, 3)
void interleave_half_kernel(const float* __restrict__ x,
                            const int* __restrict__ perm,
                            float* __restrict__ out,
                            int L) {
    extern __shared__ __align__(128) unsigned char smem_raw[];
    float* srow = reinterpret_cast<float*>(smem_raw);
    uint64_t* mbar_p = reinterpret_cast<uint64_t*>(smem_raw + (size_t)L * sizeof(float));
    uint32_t mbar = (uint32_t)__cvta_generic_to_shared(mbar_p);
    uint32_t sdst = (uint32_t)__cvta_generic_to_shared(srow);

    long long row = blockIdx.x >> 1;
    int half = blockIdx.x & 1;
    int H = L >> 1;                       // elements per half
    long long base = row * (long long)L + (long long)half * H;

    const float* xrow = x + row * (long long)L;
    const int*   phalf = perm + base;
    float*       ohalf = out + base;

    int tid = threadIdx.x;
    unsigned bytes = (unsigned)L * 4u;

    if (tid == 0) {
        asm volatile("mbarrier.init.shared.b64 [%0], %1;"
                     :: "r"(mbar), "r"(1) : "memory");
    }
    __syncthreads();

    if (tid == 0) {
        asm volatile("mbarrier.arrive.expect_tx.shared.b64 _, [%0], %1;"
                     :: "r"(mbar), "r"(bytes) : "memory");
        asm volatile("cp.async.bulk.shared::cta.global.mbarrier::complete_tx::bytes "
                     "[%0], [%1], %2, [%3];"
                     :: "r"(sdst), "l"(xrow), "r"(bytes), "r"(mbar) : "memory");
    }

    // Prefetch this half's perm (H/4 = 2048 = 4 * THREADS int4s) while the
    // TMA streams the row. Read-once -> evict-first.
    const int4* p4 = reinterpret_cast<const int4*>(phalf);
    int4 p[4];
    #pragma unroll
    for (int j = 0; j < 4; j++) p[j] = __ldcs(p4 + tid + j * THREADS);

    // Wait for the row (acquire orders subsequent smem reads).
    {
        uint32_t done;
        asm volatile(
            "{\n\t.reg .pred P;\n\t"
            "mbarrier.try_wait.parity.acquire.cta.shared::cta.b64 P, [%1], %2;\n\t"
            "selp.b32 %0, 1, 0, P;\n\t}"
            : "=r"(done) : "r"(mbar), "r"(0u) : "memory");
        if (!done) {
            asm volatile(
                "{\n\t.reg .pred P;\n\t"
                "W_%=:\n\t"
                "mbarrier.try_wait.parity.acquire.cta.shared::cta.b64 P, [%0], %1, 0x989680;\n\t"
                "@P bra.uni D_%=;\n\t"
                "bra.uni W_%=;\n\t"
                "D_%=:\n\t}"
                :: "r"(mbar), "r"(0u) : "memory");
        }
    }

    // Gather from SMEM, streaming stores (evict-first).
    float4* o4 = reinterpret_cast<float4*>(ohalf);
    #pragma unroll
    for (int j = 0; j < 4; j++) {
        float4 o;
        o.x = srow[p[j].x];
        o.y = srow[p[j].y];
        o.z = srow[p[j].z];
        o.w = srow[p[j].w];
        __stcs(o4 + tid + j * THREADS, o);
    }
}

extern "C" void kernel_launch(void* const* d_in, const int* in_sizes, int n_in,
                              void* d_out, int out_size) {
    const float* x   = (const float*)d_in[0];
    const int* perm  = (const int*)d_in[1];
    float* out       = (float*)d_out;

    long long total = (long long)in_sizes[1];
    int B = 1024;
    int L = (int)(total / B);

    size_t smem = (size_t)L * sizeof(float) + 16;  // full row + mbarrier
    cudaFuncSetAttribute(interleave_half_kernel,
                         cudaFuncAttributeMaxDynamicSharedMemorySize, (int)smem);

    interleave_half_kernel<<<2 * B, THREADS, smem>>>(x, perm, out, L);
}